// round 15
// baseline (speedup 1.0000x reference)
#include <cuda_runtime.h>

// x: [32, 256, 64, 64] f32; weight: [256, 256, 3, 3] f32; bias: [256] f32
// out: [32, 256, 1, 1] f32   (spatial = 128*128 = 16384)
#define B_   32
#define C_   256
#define O_   256
#define HW_  4096            // 64*64
#define BC_  (B_ * C_)       // 8192 images
#define NPAIR (BC_ / 2)      // 4096 stats blocks, 2 images each

// Kernel-B tiling: block = (8 o's) x (16 channels), grid = 32*16 = 512
#define OT_  8
#define QC_  16
#define NOT_ (O_ / OT_)      // 32 o-tiles
#define NQ_  (C_ / QC_)      // 16 channel-tiles

// Scratch (no allocations). g_done zero-init at load; reset each launch.
__device__ float4 g_statsT[BC_];              // [c][b] -> (T, R0, C0, x00)
__device__ float  g_part[NOT_][NQ_][OT_][B_]; // partial sums
__device__ unsigned int g_done[NOT_ * 32];    // per-o-tile ctr, line-padded

// acq_rel fetch-add: releases prior stores, acquires others'; NO CCTL.IVALL
__device__ __forceinline__ unsigned int acqrel_add(unsigned int* p) {
    unsigned int v;
    asm volatile("atom.acq_rel.gpu.add.u32 %0, [%1], %2;"
                 : "=r"(v) : "l"(p), "r"(1u) : "memory");
    return v;
}

// ---------------------------------------------------------------------------
// Kernel A: stats, TWO images per block (4096 blocks x 32 KB).
// All 8 float4 loads front-batched -> 2x in-flight bytes per warp vs the
// 1-image version; block/wave/scheduling overhead halved. Final reduction
// done in parallel: warp 0 reduces image 0, warp 1 reduces image 1.
// PDL trigger at block start (dependent gemm launch schedulable at last wave).
// ---------------------------------------------------------------------------
__global__ void __launch_bounds__(256) stats_kernel(const float* __restrict__ x) {
    cudaTriggerProgrammaticLaunchCompletion();

    const int pair = blockIdx.x;
    const int t = threadIdx.x;
    const float4* __restrict__ p0 =
        reinterpret_cast<const float4*>(x + (size_t)pair * 2 * HW_);
    const float4* __restrict__ p1 = p0 + (HW_ / 4);

    // front-batch ALL 8 independent LDG.128 (2 images x 4)
    float4 a[4], bb[4];
    #pragma unroll
    for (int i = 0; i < 4; i++) a[i]  = __ldcs(&p0[t + i * 256]);
    #pragma unroll
    for (int i = 0; i < 4; i++) bb[i] = __ldcs(&p1[t + i * 256]);

    float s0 = 0.f, r0a = 0.f, c0a = 0.f, v0a = 0.f;
    float s1 = 0.f, r0b = 0.f, c0b = 0.f, v0b = 0.f;

    #pragma unroll
    for (int i = 0; i < 4; i++) {
        const int j = t + i * 256;            // float4 index 0..1023
        float va = a[i].x + a[i].y + a[i].z + a[i].w;
        float vb = bb[i].x + bb[i].y + bb[i].z + bb[i].w;
        s0 += va;
        s1 += vb;
        if (j < 16)        { r0a += va; r0b += vb; }   // row 0
        if ((j & 15) == 0) { c0a += a[i].x; c0b += bb[i].x; }  // col 0
        if (j == 0)        { v0a = a[i].x;  v0b = bb[i].x; }
    }

    // warp reduce (6 values)
    #pragma unroll
    for (int off = 16; off > 0; off >>= 1) {
        s0  += __shfl_xor_sync(0xFFFFFFFFu, s0,  off);
        r0a += __shfl_xor_sync(0xFFFFFFFFu, r0a, off);
        c0a += __shfl_xor_sync(0xFFFFFFFFu, c0a, off);
        s1  += __shfl_xor_sync(0xFFFFFFFFu, s1,  off);
        r0b += __shfl_xor_sync(0xFFFFFFFFu, r0b, off);
        c0b += __shfl_xor_sync(0xFFFFFFFFu, c0b, off);
    }

    __shared__ float ss0[8], sr0[8], sc0[8];
    __shared__ float ss1[8], sr1[8], sc1[8];
    __shared__ float sv0, sv1;
    const int warp = t >> 5, lane = t & 31;
    if (t == 0) { sv0 = v0a; sv1 = v0b; }
    if (lane == 0) {
        ss0[warp] = s0; sr0[warp] = r0a; sc0[warp] = c0a;
        ss1[warp] = s1; sr1[warp] = r0b; sc1[warp] = c0b;
    }
    __syncthreads();

    // parallel final reduce: warp 0 -> image 0, warp 1 -> image 1
    if (warp < 2) {
        const float* fss = (warp == 0) ? ss0 : ss1;
        const float* fsr = (warp == 0) ? sr0 : sr1;
        const float* fsc = (warp == 0) ? sc0 : sc1;
        float fs = (lane < 8) ? fss[lane] : 0.f;
        float fr = (lane < 8) ? fsr[lane] : 0.f;
        float fc = (lane < 8) ? fsc[lane] : 0.f;
        #pragma unroll
        for (int off = 4; off > 0; off >>= 1) {
            fs += __shfl_xor_sync(0xFFFFFFFFu, fs, off);
            fr += __shfl_xor_sync(0xFFFFFFFFu, fr, off);
            fc += __shfl_xor_sync(0xFFFFFFFFu, fc, off);
        }
        if (lane == 0) {
            const int bc = pair * 2 + warp;   // image index
            const int b = bc >> 8;
            const int c = bc & 255;
            const float v00 = (warp == 0) ? sv0 : sv1;
            g_statsT[c * B_ + b] = make_float4(fs, fr, fc, v00);
        }
    }
}

// ---------------------------------------------------------------------------
// Kernel B (UNCHANGED from R14 — best measured): PDL secondary, 512 blocks.
//   PRE-SYNC: fold raw 3x3 weights -> smem, load bias (inputs only).
//   cudaGridDependencySynchronize(), then 16 front-batched stats loads,
//   dot4, partial store, acq_rel election, fixed-order combine, epilogue.
// ---------------------------------------------------------------------------
__global__ void __launch_bounds__(256) gemm_kernel(const float* __restrict__ w,
                                                   const float* __restrict__ bias,
                                                   float* __restrict__ out) {
    const int ot = blockIdx.x >> 4;        // / NQ_
    const int q  = blockIdx.x & (NQ_ - 1);
    const int t  = threadIdx.x;
    const int obase = ot * OT_;
    const int cbase = q * QC_;

    const int o_l = t >> 5;                // warp = local o
    const int b   = t & 31;                // lane = batch

    __shared__ float4 wsm[OT_][QC_];       // [o_local][c_local]
    __shared__ float  bsm[OT_];
    __shared__ unsigned int s_old;

    // ---- PRE-SYNC: fold weights (inputs only; hidden under A's tail) ----
    if (t < QC_ * OT_) {
        const int c_l = t >> 3;            // / OT_
        const int oo  = t & (OT_ - 1);
        const float* p = w + ((size_t)(cbase + c_l) * O_ + (obase + oo)) * 9;
        float w00 = __ldg(p + 0), w01 = __ldg(p + 1), w02 = __ldg(p + 2);
        float w10 = __ldg(p + 3), w11 = __ldg(p + 4), w12 = __ldg(p + 5);
        float w20 = __ldg(p + 6), w21 = __ldg(p + 7), w22 = __ldg(p + 8);
        float wsum = ((w00 + w01) + (w02 + w10)) + ((w11 + w12) + (w20 + w21)) + w22;
        float wkh0 = w00 + w01 + w02;      // kh == 0 row
        float wkw0 = w00 + w10 + w20;      // kw == 0 col
        wsm[oo][c_l] = make_float4(wsum, -wkh0, -wkw0, w00);
    } else if (t < QC_ * OT_ + OT_) {
        const int oo = t - QC_ * OT_;
        bsm[oo] = __ldg(&bias[obase + oo]);
    }

    // ---- wait for kernel A (hardware dependency, not a spin) ----
    cudaGridDependencySynchronize();

    // ---- POST-SYNC: front-batched stats loads (16 independent LDG.128) ----
    float4 a[QC_];
    #pragma unroll
    for (int k = 0; k < QC_; k++)
        a[k] = g_statsT[(cbase + k) * B_ + b];

    __syncthreads();                       // wsm/bsm visible

    float acc0 = 0.f, acc1 = 0.f;
    #pragma unroll
    for (int k = 0; k < QC_; k += 2) {
        const float4 w0 = wsm[o_l][k];
        const float4 w1 = wsm[o_l][k + 1];
        acc0 = fmaf(a[k].x, w0.x, acc0);
        acc1 = fmaf(a[k + 1].x, w1.x, acc1);
        acc0 = fmaf(a[k].y, w0.y, acc0);
        acc1 = fmaf(a[k + 1].y, w1.y, acc1);
        acc0 = fmaf(a[k].z, w0.z, acc0);
        acc1 = fmaf(a[k + 1].z, w1.z, acc1);
        acc0 = fmaf(a[k].w, w0.w, acc0);
        acc1 = fmaf(a[k + 1].w, w1.w, acc1);
    }
    g_part[ot][q][o_l][b] = acc0 + acc1;   // coalesced 128 B per warp

    // ---- election (acq_rel orders partial stores; no CCTL) ----
    __syncthreads();
    if (t == 0) s_old = acqrel_add(&g_done[ot * 32]);
    __syncthreads();

    if (s_old == (unsigned int)NQ_ - 1u) { // last block for this o-tile
        float p[NQ_];
        #pragma unroll
        for (int qq = 0; qq < NQ_; qq++)   // front-batched L2-hot loads
            p[qq] = __ldcg(&g_part[ot][qq][o_l][b]);
        float sacc = 0.f;
        #pragma unroll
        for (int qq = 0; qq < NQ_; qq++)   // fixed order -> deterministic
            sacc += p[qq];
        const int o = obase + o_l;
        out[b * O_ + o] = 2.0f * (sacc * (1.0f / 16384.0f) + bsm[o_l]);
        if (t == 0) atomicExch(&g_done[ot * 32], 0u);   // replay-safe reset
    }
}

// ---------------------------------------------------------------------------
extern "C" void kernel_launch(void* const* d_in, const int* in_sizes, int n_in,
                              void* d_out, int out_size) {
    const float* x    = (const float*)d_in[0];
    const float* wgt  = (const float*)d_in[1];
    const float* bias = (const float*)d_in[2];
    float* out        = (float*)d_out;

    stats_kernel<<<NPAIR, 256>>>(x);

    // PDL secondary: may begin while the stats kernel drains.
    cudaLaunchConfig_t cfg = {};
    cfg.gridDim  = dim3(NOT_ * NQ_, 1, 1);
    cfg.blockDim = dim3(256, 1, 1);
    cfg.dynamicSmemBytes = 0;
    cudaLaunchAttribute attr[1];
    attr[0].id = cudaLaunchAttributeProgrammaticStreamSerialization;
    attr[0].val.programmaticStreamSerializationAllowed = 1;
    cfg.attrs = attr;
    cfg.numAttrs = 1;
    cudaLaunchKernelEx(&cfg, gemm_kernel, wgt, bias, out);
}

// round 17
// speedup vs baseline: 1.0625x; 1.0625x over previous
#include <cuda_runtime.h>

// x: [32, 256, 64, 64] f32; weight: [256, 256, 3, 3] f32; bias: [256] f32
// out: [32, 256, 1, 1] f32   (spatial = 128*128 = 16384)
#define B_   32
#define C_   256
#define O_   256
#define HW_  4096            // 64*64
#define BC_  (B_ * C_)       // 8192 stats blocks (kernel A grid)

// Kernel-B tiling: block = (8 o's) x (16 channels), grid = 32*16 = 512
#define OT_  8
#define QC_  16
#define NOT_ (O_ / OT_)      // 32 o-tiles
#define NQ_  (C_ / QC_)      // 16 channel-tiles

// Scratch (no allocations). g_done zero-init at load; reset each launch.
__device__ float4 g_statsT[BC_];              // [c][b] -> (T, R0, C0, x00)
__device__ float  g_part[NOT_][NQ_][OT_][B_]; // partial sums
__device__ unsigned int g_done[NOT_ * 32];    // per-o-tile ctr, line-padded

// acq_rel fetch-add: releases prior stores, acquires others'; NO CCTL.IVALL
__device__ __forceinline__ unsigned int acqrel_add(unsigned int* p) {
    unsigned int v;
    asm volatile("atom.acq_rel.gpu.add.u32 %0, [%1], %2;"
                 : "=r"(v) : "l"(p), "r"(1u) : "memory");
    return v;
}

// ---------------------------------------------------------------------------
// Kernel A (R14 config — fastest measured): pure stats stream.
// One block per (b,c) 16 KB image, 256 threads, 4x float4 (__ldcs).
// PDL trigger at block start: dependent gemm launch becomes schedulable
// when A's last wave begins.
// ---------------------------------------------------------------------------
__global__ void __launch_bounds__(256) stats_kernel(const float* __restrict__ x) {
    cudaTriggerProgrammaticLaunchCompletion();

    const int bc = blockIdx.x;
    const float4* __restrict__ p4 =
        reinterpret_cast<const float4*>(x + (size_t)bc * HW_);
    const int t = threadIdx.x;

    float s = 0.f, r0 = 0.f, c0 = 0.f, v00 = 0.f;

    #pragma unroll
    for (int i = 0; i < 4; i++) {
        const int j = t + i * 256;        // float4 index 0..1023
        float4 v = __ldcs(&p4[j]);        // streaming, read-once
        float vs = v.x + v.y + v.z + v.w;
        s += vs;
        if (j < 16)          r0 += vs;    // row 0 = first 64 elems
        if ((j & 15) == 0)   c0 += v.x;   // col 0 = elem % 64 == 0
        if (j == 0)          v00 = v.x;
    }

    #pragma unroll
    for (int off = 16; off > 0; off >>= 1) {
        s  += __shfl_xor_sync(0xFFFFFFFFu, s,  off);
        r0 += __shfl_xor_sync(0xFFFFFFFFu, r0, off);
        c0 += __shfl_xor_sync(0xFFFFFFFFu, c0, off);
    }

    __shared__ float ss[8], sr[8], sc[8];
    __shared__ float sv00;
    const int warp = t >> 5, lane = t & 31;
    if (t == 0) sv00 = v00;
    if (lane == 0) { ss[warp] = s; sr[warp] = r0; sc[warp] = c0; }
    __syncthreads();

    if (warp == 0) {
        float fs = (lane < 8) ? ss[lane] : 0.f;
        float fr = (lane < 8) ? sr[lane] : 0.f;
        float fc = (lane < 8) ? sc[lane] : 0.f;
        #pragma unroll
        for (int off = 4; off > 0; off >>= 1) {
            fs += __shfl_xor_sync(0xFFFFFFFFu, fs, off);
            fr += __shfl_xor_sync(0xFFFFFFFFu, fr, off);
            fc += __shfl_xor_sync(0xFFFFFFFFu, fc, off);
        }
        if (lane == 0) {
            const int b = bc >> 8;
            const int c = bc & 255;
            g_statsT[c * B_ + b] = make_float4(fs, fr, fc, sv00);
        }
    }
}

// ---------------------------------------------------------------------------
// Kernel B (R14 config): PDL secondary, 512 blocks.
//   PRE-SYNC: fold raw 3x3 weights -> smem, load bias (inputs only,
//             overlapped with A's drain).
//   cudaGridDependencySynchronize(), then 16 front-batched stats loads,
//   dot4, partial store, acq_rel election, fixed-order combine, epilogue.
// ---------------------------------------------------------------------------
__global__ void __launch_bounds__(256) gemm_kernel(const float* __restrict__ w,
                                                   const float* __restrict__ bias,
                                                   float* __restrict__ out) {
    const int ot = blockIdx.x >> 4;        // / NQ_
    const int q  = blockIdx.x & (NQ_ - 1);
    const int t  = threadIdx.x;
    const int obase = ot * OT_;
    const int cbase = q * QC_;

    const int o_l = t >> 5;                // warp = local o
    const int b   = t & 31;                // lane = batch

    __shared__ float4 wsm[OT_][QC_];       // [o_local][c_local]
    __shared__ float  bsm[OT_];
    __shared__ unsigned int s_old;

    // ---- PRE-SYNC: fold weights (inputs only; hidden under A's tail) ----
    if (t < QC_ * OT_) {
        const int c_l = t >> 3;            // / OT_
        const int oo  = t & (OT_ - 1);
        const float* p = w + ((size_t)(cbase + c_l) * O_ + (obase + oo)) * 9;
        float w00 = __ldg(p + 0), w01 = __ldg(p + 1), w02 = __ldg(p + 2);
        float w10 = __ldg(p + 3), w11 = __ldg(p + 4), w12 = __ldg(p + 5);
        float w20 = __ldg(p + 6), w21 = __ldg(p + 7), w22 = __ldg(p + 8);
        float wsum = ((w00 + w01) + (w02 + w10)) + ((w11 + w12) + (w20 + w21)) + w22;
        float wkh0 = w00 + w01 + w02;      // kh == 0 row
        float wkw0 = w00 + w10 + w20;      // kw == 0 col
        wsm[oo][c_l] = make_float4(wsum, -wkh0, -wkw0, w00);
    } else if (t < QC_ * OT_ + OT_) {
        const int oo = t - QC_ * OT_;
        bsm[oo] = __ldg(&bias[obase + oo]);
    }

    // ---- wait for kernel A (hardware dependency, not a spin) ----
    cudaGridDependencySynchronize();

    // ---- POST-SYNC: front-batched stats loads (16 independent LDG.128) ----
    float4 a[QC_];
    #pragma unroll
    for (int k = 0; k < QC_; k++)
        a[k] = g_statsT[(cbase + k) * B_ + b];

    __syncthreads();                       // wsm/bsm visible

    float acc0 = 0.f, acc1 = 0.f;
    #pragma unroll
    for (int k = 0; k < QC_; k += 2) {
        const float4 w0 = wsm[o_l][k];
        const float4 w1 = wsm[o_l][k + 1];
        acc0 = fmaf(a[k].x, w0.x, acc0);
        acc1 = fmaf(a[k + 1].x, w1.x, acc1);
        acc0 = fmaf(a[k].y, w0.y, acc0);
        acc1 = fmaf(a[k + 1].y, w1.y, acc1);
        acc0 = fmaf(a[k].z, w0.z, acc0);
        acc1 = fmaf(a[k + 1].z, w1.z, acc1);
        acc0 = fmaf(a[k].w, w0.w, acc0);
        acc1 = fmaf(a[k + 1].w, w1.w, acc1);
    }
    g_part[ot][q][o_l][b] = acc0 + acc1;   // coalesced 128 B per warp

    // ---- election (acq_rel orders partial stores; no CCTL) ----
    __syncthreads();
    if (t == 0) s_old = acqrel_add(&g_done[ot * 32]);
    __syncthreads();

    if (s_old == (unsigned int)NQ_ - 1u) { // last block for this o-tile
        float p[NQ_];
        #pragma unroll
        for (int qq = 0; qq < NQ_; qq++)   // front-batched L2-hot loads
            p[qq] = __ldcg(&g_part[ot][qq][o_l][b]);
        float sacc = 0.f;
        #pragma unroll
        for (int qq = 0; qq < NQ_; qq++)   // fixed order -> deterministic
            sacc += p[qq];
        const int o = obase + o_l;
        out[b * O_ + o] = 2.0f * (sacc * (1.0f / 16384.0f) + bsm[o_l]);
        if (t == 0) atomicExch(&g_done[ot * 32], 0u);   // replay-safe reset
    }
}

// ---------------------------------------------------------------------------
extern "C" void kernel_launch(void* const* d_in, const int* in_sizes, int n_in,
                              void* d_out, int out_size) {
    const float* x    = (const float*)d_in[0];
    const float* wgt  = (const float*)d_in[1];
    const float* bias = (const float*)d_in[2];
    float* out        = (float*)d_out;

    stats_kernel<<<BC_, 256>>>(x);

    // PDL secondary: may begin while the stats kernel drains.
    cudaLaunchConfig_t cfg = {};
    cfg.gridDim  = dim3(NOT_ * NQ_, 1, 1);
    cfg.blockDim = dim3(256, 1, 1);
    cfg.dynamicSmemBytes = 0;
    cudaLaunchAttribute attr[1];
    attr[0].id = cudaLaunchAttributeProgrammaticStreamSerialization;
    attr[0].val.programmaticStreamSerializationAllowed = 1;
    cfg.attrs = attr;
    cfg.numAttrs = 1;
    cudaLaunchKernelEx(&cfg, gemm_kernel, wgt, bias, out);
}